// round 1
// baseline (speedup 1.0000x reference)
#include <cuda_runtime.h>
#include <math.h>
#include <math_constants.h>

#define BATCH 32
#define NP 128
#define NG 64
#define NDIM 3

// per-sample (coord_loss + exist_loss), filled by match kernel
__device__ float g_partial[BATCH];

// ---------------------------------------------------------------------------
// One CTA per sample. 128 threads build cost matrix + epilogue; warp 0 runs
// the Jonker-Volgenant shortest-augmenting-path LSA in float64 (matches the
// numpy reference bit-for-bit in the decision path).
// Cost matrix layout matches the reference's transposed view:
//   C[gt][pred], n=64 rows (gt), m=128 cols (pred).
// ---------------------------------------------------------------------------
__global__ __launch_bounds__(NP, 1)
void match_loss_kernel(const float* __restrict__ pred,   // [B,NP,3]
                       const float* __restrict__ eprob,  // [B,NP]
                       const float* __restrict__ gt,     // [B,NG,3]
                       const float* __restrict__ weight) // [NP]
{
    __shared__ float  Cf[NG * NP];        // 32 KB, fp32 costs (exact ref values)
    __shared__ float  sp[NP * NDIM];
    __shared__ float  sg[NG * NDIM];
    __shared__ double v[NP + 1];
    __shared__ double minv[NP + 1];
    __shared__ double u[NG + 1];
    __shared__ int    p[NP + 1];          // p[j] = 1-based row matched to col j
    __shared__ int    way[NP + 1];
    __shared__ unsigned char used[NP + 4];
    __shared__ float  red[2 * NP];

    const int b = blockIdx.x;
    const int t = threadIdx.x;

    // --- load coords to shared ---
    for (int i = t; i < NP * NDIM; i += NP) sp[i] = pred[b * NP * NDIM + i];
    for (int i = t; i < NG * NDIM; i += NP) sg[i] = gt[b * NG * NDIM + i];
    __syncthreads();

    // --- cost matrix: fp32 euclidean distance, identical to np.linalg.norm(f32)
    for (int i = t; i < NG * NP; i += NP) {
        int g = i >> 7;        // / NP
        int q = i & (NP - 1);  // % NP
        float dx = sp[q * 3 + 0] - sg[g * 3 + 0];
        float dy = sp[q * 3 + 1] - sg[g * 3 + 1];
        float dz = sp[q * 3 + 2] - sg[g * 3 + 2];
        Cf[i] = sqrtf(dx * dx + dy * dy + dz * dz);
    }

    // --- init LSA state ---
    for (int j = t; j <= NP; j += NP) { }   // (NP+1 <= 129, handled below)
    if (t <= NP) { v[t] = 0.0; p[t] = 0; way[t] = 0; }
    if (t == 0) { v[NP] = 0.0; p[NP] = 0; way[NP] = 0; }  // t covers 0..127; j=128 by t==0
    if (t <= NG) u[t] = 0.0;
    __syncthreads();

    // --- JV shortest augmenting path: warp 0 only ---
    if (t < 32) {
        const unsigned full = 0xffffffffu;
        for (int i = 1; i <= NG; i++) {
            // per-row reset
            #pragma unroll
            for (int k = 0; k < 4; k++) {
                int j = t + 1 + 32 * k;           // 1..128
                minv[j] = CUDART_INF;
                used[j] = 0;
            }
            if (t == 0) { p[0] = i; used[0] = 0; }
            __syncwarp(full);

            int j0 = 0;
            while (true) {
                if (t == 0) used[j0] = 1;
                __syncwarp(full);
                const int    i0  = p[j0];
                const double ui0 = u[i0];
                const float* crow = &Cf[(i0 - 1) * NP];

                double bestv = CUDART_INF;
                int    bestj = NP + 1;
                #pragma unroll
                for (int k = 0; k < 4; k++) {
                    int j = t + 1 + 32 * k;
                    if (!used[j]) {
                        double cur = (double)crow[j - 1] - ui0 - v[j];
                        if (cur < minv[j]) { minv[j] = cur; way[j] = j0; }
                        double mj = minv[j];
                        if (mj < bestv) { bestv = mj; bestj = j; } // ascending j: strict < keeps min index
                    }
                }
                // warp argmin with numpy tie-break (min value, then min index)
                #pragma unroll
                for (int off = 16; off; off >>= 1) {
                    double ov = __shfl_xor_sync(full, bestv, off);
                    int    oj = __shfl_xor_sync(full, bestj, off);
                    if (ov < bestv || (ov == bestv && oj < bestj)) { bestv = ov; bestj = oj; }
                }
                const double delta = bestv;
                const int    j1    = bestj;

                // dual updates (distinct u[] targets per used col -> no conflicts)
                #pragma unroll
                for (int k = 0; k < 4; k++) {
                    int j = t + 1 + 32 * k;
                    if (used[j]) { u[p[j]] += delta; v[j] -= delta; }
                    else         { minv[j] -= delta; }
                }
                if (t == 0) { u[p[0]] += delta; v[0] -= delta; }  // virtual col 0
                __syncwarp(full);

                j0 = j1;
                if (p[j0] == 0) break;
            }
            // backtrack augmenting path
            if (t == 0) {
                int jj = j0;
                while (jj) { int j1 = way[jj]; p[jj] = p[j1]; jj = j1; }
            }
            __syncwarp(full);
        }
    }
    __syncthreads();

    // --- losses: thread t == pred index q ---
    const int q  = t;
    const int pj = p[q + 1];              // 0 = unmatched, else gt row (1-based)
    float sl1 = 0.0f;
    float mask = 0.0f;
    if (pj != 0) {
        mask = 1.0f;
        const int g = pj - 1;
        #pragma unroll
        for (int d = 0; d < 3; d++) {
            float diff = fabsf(sp[q * 3 + d] - sg[g * 3 + d]);
            sl1 += (diff < 1.0f) ? 0.5f * diff * diff : diff - 0.5f;
        }
    }
    const float pr   = eprob[b * NP + q];
    const float lp   = fmaxf(logf(pr), -100.0f);
    const float l1p  = fmaxf(log1pf(-pr), -100.0f);
    const float bce  = -(mask * lp + (1.0f - mask) * l1p) * weight[q];

    red[t]      = sl1;
    red[NP + t] = bce;
    __syncthreads();
    #pragma unroll
    for (int s = 64; s; s >>= 1) {
        if (t < s) { red[t] += red[t + s]; red[NP + t] += red[NP + t + s]; }
        __syncthreads();
    }
    if (t == 0) {
        const float coord = red[0] / (float)(NG * NDIM);   // mean over (64,3)
        const float exist = red[NP] / (float)NP;           // mean over 128
        g_partial[b] = coord + exist;                      // COORD_W=EXIST_W=1
    }
}

// ---------------------------------------------------------------------------
// Deterministic final reduce: mean over batch of (coord+exist) plus count MSE.
// ---------------------------------------------------------------------------
__global__ void reduce_kernel(const float* __restrict__ count_pred, // [B,1]
                              const int*   __restrict__ gt_counts,  // [B]
                              float* __restrict__ out)
{
    const int t = threadIdx.x;   // 32 threads
    float part = g_partial[t];
    float cd   = count_pred[t] - (float)gt_counts[t];
    float c2   = cd * cd;
    #pragma unroll
    for (int off = 16; off; off >>= 1) {
        part += __shfl_xor_sync(0xffffffffu, part, off);
        c2   += __shfl_xor_sync(0xffffffffu, c2, off);
    }
    if (t == 0) out[0] = part / (float)BATCH + c2 / (float)BATCH;
}

extern "C" void kernel_launch(void* const* d_in, const int* in_sizes, int n_in,
                              void* d_out, int out_size)
{
    const float* pred = (const float*)d_in[0];  // pred_coords [32,128,3]
    const float* ep   = (const float*)d_in[1];  // exist_probs [32,128]
    const float* cp   = (const float*)d_in[2];  // count_pred  [32,1]
    const float* gt   = (const float*)d_in[3];  // gt_coords   [32,64,3]
    const int*   gc   = (const int*)d_in[4];    // gt_counts   [32] int32
    const float* w    = (const float*)d_in[5];  // weight      [1,128]

    match_loss_kernel<<<BATCH, NP>>>(pred, ep, gt, w);
    reduce_kernel<<<1, 32>>>(cp, gc, (float*)d_out);
}

// round 4
// speedup vs baseline: 1.5722x; 1.5722x over previous
#include <cuda_runtime.h>
#include <math.h>
#include <math_constants.h>

#define BATCH 32
#define NP 128
#define NG 64
#define NDIM 3
#define FULLM 0xffffffffu

// per-sample (coord_loss + exist_loss), filled by match kernel
__device__ float g_partial[BATCH];

// ---------------------------------------------------------------------------
// One CTA per sample. 128 threads build the cost matrix + run the epilogue;
// warp 0 runs shortest-augmenting-path LSA (f64) with greedy dual init.
// Cost layout (transposed view, as in the reference _lsa): C[gt][pred],
// n = 64 rows (gt), m = 128 cols (pred). Each lane of warp 0 owns the 4
// columns j-1 = 4*lane+k; per-column state lives in registers.
// ---------------------------------------------------------------------------
__global__ __launch_bounds__(NP, 1)
void match_loss_kernel(const float* __restrict__ pred,   // [B,NP,3]
                       const float* __restrict__ eprob,  // [B,NP]
                       const float* __restrict__ gt,     // [B,NG,3]
                       const float* __restrict__ weight) // [NP]
{
    __shared__ float  Cf[NG * NP];        // 32 KB fp32 costs (exact ref values)
    __shared__ float  sp[NP * NDIM];
    __shared__ float  sg[NG * NDIM];
    __shared__ double u_sh[NG + 1];
    __shared__ int    p_sh[NP + 1];       // p[j] = 1-based row matched to col j
    __shared__ int    way_sh[NP + 1];
    __shared__ float  rminv[NG];
    __shared__ int    rargj[NG];          // 0-based argmin col of each row
    __shared__ int    rfree[NG + 1];      // 1 = row still unassigned after greedy
    __shared__ float  red[2 * NP];

    const int b = blockIdx.x;
    const int t = threadIdx.x;

    // --- load coords to shared ---
    for (int i = t; i < NP * NDIM; i += NP) sp[i] = pred[b * NP * NDIM + i];
    for (int i = t; i < NG * NDIM; i += NP) sg[i] = gt[b * NG * NDIM + i];
    if (t <= NP) p_sh[t] = 0;
    if (t == 0)  p_sh[NP] = 0;
    __syncthreads();

    // --- cost matrix: fp32 euclidean distance (identical to np.linalg.norm f32)
    for (int i = t; i < NG * NP; i += NP) {
        int g = i >> 7;
        int q = i & (NP - 1);
        float dx = sp[q * 3 + 0] - sg[g * 3 + 0];
        float dy = sp[q * 3 + 1] - sg[g * 3 + 1];
        float dz = sp[q * 3 + 2] - sg[g * 3 + 2];
        Cf[i] = sqrtf(dx * dx + dy * dy + dz * dz);
    }
    __syncthreads();

    // --- row minima (for greedy dual init) ---
    if (t < NG) {
        const float* r = &Cf[t * NP];
        float bv = r[0]; int bj = 0;
        #pragma unroll 8
        for (int j = 1; j < NP; j++) {
            float c = r[j];
            if (c < bv) { bv = c; bj = j; }
        }
        rminv[t] = bv; rargj[t] = bj;
    }
    __syncthreads();

    // --- greedy tight pre-assignment: u[i]=rowmin, v[j]=0 (dual feasible) ---
    if (t == 0) {
        u_sh[0] = 0.0;
        for (int i = 1; i <= NG; i++) {
            u_sh[i] = (double)rminv[i - 1];
            int j = rargj[i - 1] + 1;
            if (p_sh[j] == 0) { p_sh[j] = i; rfree[i] = 0; }
            else              { rfree[i] = 1; }
        }
    }
    __syncthreads();

    // --- shortest augmenting path for leftover rows: warp 0 only ---
    if (t < 32) {
        double v0 = 0.0, v1 = 0.0, v2 = 0.0, v3 = 0.0;     // v[4t+k+1]
        const float* cbase = &Cf[4 * t];

        for (int i = 1; i <= NG; i++) {
            if (rfree[i] == 0) continue;

            double m0 = CUDART_INF, m1 = CUDART_INF, m2 = CUDART_INF, m3 = CUDART_INF;
            double d0 = 0.0, d1 = 0.0, d2 = 0.0, d3 = 0.0;  // per-slot delta sums
            int    r0 = 0, r1 = 0, r2 = 0, r3 = 0;          // matched row per used slot
            unsigned unused = 0xFu;
            double Dtot = 0.0;

            int    i0   = i;
            double u_i0 = u_sh[i];
            int    j0   = 0;
            int    jfin = 0;

            // defensive cap: a correct run augments within <= NP+1 steps
            for (int step = 0; step < 2 * (NP + 1); step++) {
                const float4 c4 = *(const float4*)(cbase + (i0 - 1) * NP);

                double bestv = CUDART_INF;
                int    bestj = NP + 1;
                // scan this lane's 4 columns (mask = state at top of iteration)
                if (unused & 1u) {
                    double cur = ((double)c4.x - u_i0) - v0;
                    if (cur < m0) { m0 = cur; way_sh[4 * t + 1] = j0; }
                    if (m0 < bestv) { bestv = m0; bestj = 4 * t + 1; }
                }
                if (unused & 2u) {
                    double cur = ((double)c4.y - u_i0) - v1;
                    if (cur < m1) { m1 = cur; way_sh[4 * t + 2] = j0; }
                    if (m1 < bestv) { bestv = m1; bestj = 4 * t + 2; }
                }
                if (unused & 4u) {
                    double cur = ((double)c4.z - u_i0) - v2;
                    if (cur < m2) { m2 = cur; way_sh[4 * t + 3] = j0; }
                    if (m2 < bestv) { bestv = m2; bestj = 4 * t + 3; }
                }
                if (unused & 8u) {
                    double cur = ((double)c4.w - u_i0) - v3;
                    if (cur < m3) { m3 = cur; way_sh[4 * t + 4] = j0; }
                    if (m3 < bestv) { bestv = m3; bestj = 4 * t + 4; }
                }
                // warp argmin (value, then index — ties a.s. absent but cheap)
                #pragma unroll
                for (int off = 16; off; off >>= 1) {
                    double ov = __shfl_xor_sync(FULLM, bestv, off);
                    int    oj = __shfl_xor_sync(FULLM, bestj, off);
                    if (ov < bestv || (ov == bestv && oj < bestj)) { bestv = ov; bestj = oj; }
                }
                const double delta = bestv;
                const int    j1    = bestj;
                if (j1 > NP) break;   // unreachable in a correct run

                // prefetch next row + its dual (p[0..] valid incl. index 0)
                const int    i0n = p_sh[j1];
                const double u_n = u_sh[i0n];

                // dual/dist updates with the OLD mask (j1 not yet used)
                if (unused & 1u) m0 -= delta; else { v0 -= delta; d0 += delta; }
                if (unused & 2u) m1 -= delta; else { v1 -= delta; d1 += delta; }
                if (unused & 4u) m2 -= delta; else { v2 -= delta; d2 += delta; }
                if (unused & 8u) m3 -= delta; else { v3 -= delta; d3 += delta; }
                Dtot += delta;

                // mark j1 used on its owner lane; cache matched row; reset slot sum
                const int owner = (j1 - 1) >> 2;
                if (t == owner) {
                    const int slot = (j1 - 1) & 3;
                    unused &= ~(1u << slot);
                    if (slot == 0) { r0 = i0n; d0 = 0.0; }
                    else if (slot == 1) { r1 = i0n; d1 = 0.0; }
                    else if (slot == 2) { r2 = i0n; d2 = 0.0; }
                    else { r3 = i0n; d3 = 0.0; }
                }

                j0 = j1; i0 = i0n; u_i0 = u_n;
                if (i0 == 0) { jfin = j0; break; }
            }

            // write back deferred u updates (each row matched to exactly one col)
            if (!(unused & 1u) && r0 > 0) u_sh[r0] += d0;
            if (!(unused & 2u) && r1 > 0) u_sh[r1] += d1;
            if (!(unused & 4u) && r2 > 0) u_sh[r2] += d2;
            if (!(unused & 8u) && r3 > 0) u_sh[r3] += d3;
            if (t == 0) u_sh[i] += Dtot;
            __syncwarp(FULLM);

            // backtrack augmenting path (lane 0); bounded defensively
            if (t == 0) {
                int jj = jfin;
                for (int s = 0; s < NP + 1 && jj != 0; s++) {
                    int jp = way_sh[jj];
                    p_sh[jj] = (jp == 0) ? i : p_sh[jp];
                    jj = jp;
                }
            }
            __syncwarp(FULLM);
        }
    }
    __syncthreads();

    // --- losses: thread t == pred index q (identical arithmetic to R1) ---
    const int q  = t;
    const int pj = p_sh[q + 1];           // 0 = unmatched, else gt row (1-based)
    float sl1 = 0.0f;
    float mask = 0.0f;
    if (pj != 0) {
        mask = 1.0f;
        const int g = pj - 1;
        #pragma unroll
        for (int d = 0; d < 3; d++) {
            float diff = fabsf(sp[q * 3 + d] - sg[g * 3 + d]);
            sl1 += (diff < 1.0f) ? 0.5f * diff * diff : diff - 0.5f;
        }
    }
    const float pr  = eprob[b * NP + q];
    const float lp  = fmaxf(logf(pr), -100.0f);
    const float l1p = fmaxf(log1pf(-pr), -100.0f);
    const float bce = -(mask * lp + (1.0f - mask) * l1p) * weight[q];

    red[t]      = sl1;
    red[NP + t] = bce;
    __syncthreads();
    #pragma unroll
    for (int s = 64; s; s >>= 1) {
        if (t < s) { red[t] += red[t + s]; red[NP + t] += red[NP + t + s]; }
        __syncthreads();
    }
    if (t == 0) {
        const float coord = red[0] / (float)(NG * NDIM);   // mean over (64,3)
        const float exist = red[NP] / (float)NP;           // mean over 128
        g_partial[b] = coord + exist;                      // COORD_W=EXIST_W=1
    }
}

// ---------------------------------------------------------------------------
// Deterministic final reduce: mean over batch of (coord+exist) plus count MSE.
// ---------------------------------------------------------------------------
__global__ void reduce_kernel(const float* __restrict__ count_pred, // [B,1]
                              const int*   __restrict__ gt_counts,  // [B]
                              float* __restrict__ out)
{
    const int t = threadIdx.x;   // 32 threads
    float part = g_partial[t];
    float cd   = count_pred[t] - (float)gt_counts[t];
    float c2   = cd * cd;
    #pragma unroll
    for (int off = 16; off; off >>= 1) {
        part += __shfl_xor_sync(FULLM, part, off);
        c2   += __shfl_xor_sync(FULLM, c2, off);
    }
    if (t == 0) out[0] = part / (float)BATCH + c2 / (float)BATCH;
}

extern "C" void kernel_launch(void* const* d_in, const int* in_sizes, int n_in,
                              void* d_out, int out_size)
{
    const float* pred = (const float*)d_in[0];  // pred_coords [32,128,3]
    const float* ep   = (const float*)d_in[1];  // exist_probs [32,128]
    const float* cp   = (const float*)d_in[2];  // count_pred  [32,1]
    const float* gt   = (const float*)d_in[3];  // gt_coords   [32,64,3]
    const int*   gc   = (const int*)d_in[4];    // gt_counts   [32] int32
    const float* w    = (const float*)d_in[5];  // weight      [1,128]

    match_loss_kernel<<<BATCH, NP>>>(pred, ep, gt, w);
    reduce_kernel<<<1, 32>>>(cp, gc, (float*)d_out);
}

// round 6
// speedup vs baseline: 5.6633x; 3.6021x over previous
#include <cuda_runtime.h>
#include <math.h>

#define BATCH 32
#define NP 128
#define NG 64
#define NDIM 3
#define FULLM 0xffffffffu
#define SCALEF 1099511627776.0f   /* 2^40 — power of two: c*SCALEF is exact in f32 */
#define INF_LL (1LL << 62)

typedef long long ll;

// per-sample (coord_loss + exist_loss)
__device__ float g_partial[BATCH];

// ---------------------------------------------------------------------------
// One CTA per sample. Costs are exact fixed-point int64 (f32 value * 2^40,
// truncated), low 7 bits replaced by the column index (0-based). All duals /
// path labels / deltas are multiples of 128, so c - u - v carries its column
// index in the low 7 bits for free, and the warp argmin is a pure integer min
// of packed (value|index) with numpy tie-breaking built in.
// Layout (transposed view, as reference _lsa): C[gt][pred], n=64 rows (gt),
// m=128 cols (pred). Lane t of warp 0 owns columns j-1 in {4t..4t+3}.
// ---------------------------------------------------------------------------
__global__ __launch_bounds__(NP, 1)
void match_loss_kernel(const float* __restrict__ pred,   // [B,NP,3]
                       const float* __restrict__ eprob,  // [B,NP]
                       const float* __restrict__ gt,     // [B,NG,3]
                       const float* __restrict__ weight) // [NP]
{
    extern __shared__ ll Ci[];            // [NG*NP] packed costs, 64 KB dynamic
    __shared__ float4 sp4[NP];
    __shared__ float4 sg4[NG];
    __shared__ ll     u_sh[NG + 1];
    __shared__ int    p_sh[NP + 1];       // p[j] = 1-based row matched to col j
    __shared__ int    way_sh[NP + 1];
    __shared__ ll     rpack[NG];          // packed row minima
    __shared__ int    rfree[NG + 1];
    __shared__ float  red[2 * NP];

    const int b = blockIdx.x;
    const int t = threadIdx.x;

    // --- load coords (padded float4 for single-LDS access) ---
    {
        const float* pp = pred + (b * NP + t) * 3;
        sp4[t] = make_float4(pp[0], pp[1], pp[2], 0.f);
        if (t < NG) {
            const float* gg = gt + (b * NG + t) * 3;
            sg4[t] = make_float4(gg[0], gg[1], gg[2], 0.f);
        }
        p_sh[t] = 0;
        if (t == 0) p_sh[NP] = 0;
    }
    __syncthreads();

    // --- build packed int64 cost matrix + row minima in one pass ---
    // thread t handles row g = t>>1, columns (t&1)*64 .. +63
    {
        const int g = t >> 1;
        const int h = t & 1;
        const float4 sg = sg4[g];
        ll bp = INF_LL;
        ll* crow = &Ci[g * NP];
        #pragma unroll 8
        for (int k = 0; k < 64; k++) {
            const int q = h * 64 + k;
            const float4 sp = sp4[q];
            const float dx = sp.x - sg.x, dy = sp.y - sg.y, dz = sp.z - sg.z;
            const float c = sqrtf(dx * dx + dy * dy + dz * dz);
            const ll ci = (((ll)(c * SCALEF)) & ~127LL) | (ll)q;
            crow[q] = ci;
            if (ci < bp) bp = ci;          // ascending q: ties keep smaller q
        }
        const ll other = __shfl_xor_sync(FULLM, bp, 1);  // partner half, same warp
        if (other < bp) bp = other;        // h1 indices all > h0 indices: tie-safe
        if (h == 0) rpack[g] = bp;
    }
    __syncthreads();

    // --- greedy tight pre-assignment: u[i] = row min (masked), v = 0 ---
    if (t == 0) {
        u_sh[0] = 0;
        for (int i = 1; i <= NG; i++) {
            const ll rp = rpack[i - 1];
            u_sh[i] = rp & ~127LL;
            const int j = (int)(rp & 127) + 1;
            if (p_sh[j] == 0) { p_sh[j] = i; rfree[i] = 0; }
            else              { rfree[i] = 1; }
        }
    }
    __syncthreads();

    // --- shortest augmenting path for leftover rows: warp 0 only ---
    if (t < 32) {
        ll v0 = 0, v1 = 0, v2 = 0, v3 = 0;          // v[4t+k+1], multiples of 128
        const ll* cbase = &Ci[4 * t];

        for (int i = 1; i <= NG; i++) {
            if (rfree[i] == 0) continue;

            // preload matched rows + their duals for owned columns
            // (p and u are static within one Dijkstra)
            const int pk0 = p_sh[4 * t + 1], pk1 = p_sh[4 * t + 2];
            const int pk2 = p_sh[4 * t + 3], pk3 = p_sh[4 * t + 4];
            const ll  uk0 = u_sh[pk0], uk1 = u_sh[pk1];
            const ll  uk2 = u_sh[pk2], uk3 = u_sh[pk3];

            ll m0 = INF_LL, m1 = INF_LL, m2 = INF_LL, m3 = INF_LL;
            ll d0 = 0, d1 = 0, d2 = 0, d3 = 0;      // deferred u deltas per slot
            unsigned unused = 0xFu;
            ll Dtot = 0;

            int i0 = i;
            ll  u0 = u_sh[i];
            int j0 = 0;
            int jfin = 0;

            for (int step = 0; step < 2 * (NP + 1); step++) {     // defensive cap
                const ll* cr = cbase + (i0 - 1) * NP;
                const longlong2 ca = *(const longlong2*)(cr);
                const longlong2 cb = *(const longlong2*)(cr + 2);

                // scan owned columns: cur keeps column index in low 7 bits
                if (unused & 1u) { ll cur = ca.x - u0 - v0; if (cur < m0) { m0 = cur; way_sh[4 * t + 1] = j0; } }
                if (unused & 2u) { ll cur = ca.y - u0 - v1; if (cur < m1) { m1 = cur; way_sh[4 * t + 2] = j0; } }
                if (unused & 4u) { ll cur = cb.x - u0 - v2; if (cur < m2) { m2 = cur; way_sh[4 * t + 3] = j0; } }
                if (unused & 8u) { ll cur = cb.y - u0 - v3; if (cur < m3) { m3 = cur; way_sh[4 * t + 4] = j0; } }

                // intra-lane tournament then 5-level integer warp min
                const ll ba = m0 < m1 ? m0 : m1;
                const ll bb = m2 < m3 ? m2 : m3;
                ll best = ba < bb ? ba : bb;
                #pragma unroll
                for (int off = 16; off; off >>= 1) {
                    const ll o = __shfl_xor_sync(FULLM, best, off);
                    if (o < best) best = o;
                }
                const ll  delta = best & ~127LL;
                const int j1    = (int)(best & 127) + 1;

                // owner broadcasts (p[j1], u[p[j1]]) from registers
                const int owner = (j1 - 1) >> 2;
                const int slot  = (j1 - 1) & 3;
                int pv; ll uv;
                if      (slot == 0) { pv = pk0; uv = uk0; }
                else if (slot == 1) { pv = pk1; uv = uk1; }
                else if (slot == 2) { pv = pk2; uv = uk2; }
                else                { pv = pk3; uv = uk3; }
                const int i0n = __shfl_sync(FULLM, pv, owner);
                const ll  u_n = __shfl_sync(FULLM, uv, owner);

                // updates with the OLD mask (j1 unused at update time):
                // minv -= delta for all (used slots hold INF-ish, harmless);
                // v -= delta and deferred u += delta for used slots.
                m0 -= delta; m1 -= delta; m2 -= delta; m3 -= delta;
                if (!(unused & 1u)) { v0 -= delta; d0 += delta; }
                if (!(unused & 2u)) { v1 -= delta; d1 += delta; }
                if (!(unused & 4u)) { v2 -= delta; d2 += delta; }
                if (!(unused & 8u)) { v3 -= delta; d3 += delta; }
                Dtot += delta;

                // mark j1 used on its owner lane
                if (t == owner) {
                    unused &= ~(1u << slot);
                    if      (slot == 0) m0 = INF_LL;
                    else if (slot == 1) m1 = INF_LL;
                    else if (slot == 2) m2 = INF_LL;
                    else                m3 = INF_LL;
                }

                j0 = j1; i0 = i0n; u0 = u_n;
                if (i0 == 0) { jfin = j0; break; }
            }

            // write back deferred u updates (distinct rows per used column)
            if (!(unused & 1u) && pk0 > 0) u_sh[pk0] += d0;
            if (!(unused & 2u) && pk1 > 0) u_sh[pk1] += d1;
            if (!(unused & 4u) && pk2 > 0) u_sh[pk2] += d2;
            if (!(unused & 8u) && pk3 > 0) u_sh[pk3] += d3;
            if (t == 0) u_sh[i] += Dtot;
            __syncwarp(FULLM);

            // backtrack augmenting path (lane 0); bounded defensively
            if (t == 0) {
                int jj = jfin;
                for (int s = 0; s < NP + 1 && jj != 0; s++) {
                    const int jp = way_sh[jj];
                    p_sh[jj] = (jp == 0) ? i : p_sh[jp];
                    jj = jp;
                }
            }
            __syncwarp(FULLM);
        }
    }
    __syncthreads();

    // --- losses: thread t == pred index q (identical arithmetic to R1/R4) ---
    const int q  = t;
    const int pj = p_sh[q + 1];           // 0 = unmatched, else gt row (1-based)
    float sl1 = 0.0f;
    float mask = 0.0f;
    if (pj != 0) {
        mask = 1.0f;
        const float4 sp = sp4[q];
        const float4 sg = sg4[pj - 1];
        float dd;
        dd = fabsf(sp.x - sg.x); sl1 += (dd < 1.0f) ? 0.5f * dd * dd : dd - 0.5f;
        dd = fabsf(sp.y - sg.y); sl1 += (dd < 1.0f) ? 0.5f * dd * dd : dd - 0.5f;
        dd = fabsf(sp.z - sg.z); sl1 += (dd < 1.0f) ? 0.5f * dd * dd : dd - 0.5f;
    }
    const float pr  = eprob[b * NP + q];
    const float lp  = fmaxf(logf(pr), -100.0f);
    const float l1p = fmaxf(log1pf(-pr), -100.0f);
    const float bce = -(mask * lp + (1.0f - mask) * l1p) * weight[q];

    red[t]      = sl1;
    red[NP + t] = bce;
    __syncthreads();
    #pragma unroll
    for (int s = 64; s; s >>= 1) {
        if (t < s) { red[t] += red[t + s]; red[NP + t] += red[NP + t + s]; }
        __syncthreads();
    }
    if (t == 0) {
        const float coord = red[0] / (float)(NG * NDIM);   // mean over (64,3)
        const float exist = red[NP] / (float)NP;           // mean over 128
        g_partial[b] = coord + exist;                      // COORD_W=EXIST_W=1
    }
}

// ---------------------------------------------------------------------------
// Deterministic final reduce: mean over batch of (coord+exist) plus count MSE.
// ---------------------------------------------------------------------------
__global__ void reduce_kernel(const float* __restrict__ count_pred, // [B,1]
                              const int*   __restrict__ gt_counts,  // [B]
                              float* __restrict__ out)
{
    const int t = threadIdx.x;   // 32 threads
    float part = g_partial[t];
    const float cd = count_pred[t] - (float)gt_counts[t];
    float c2 = cd * cd;
    #pragma unroll
    for (int off = 16; off; off >>= 1) {
        part += __shfl_xor_sync(FULLM, part, off);
        c2   += __shfl_xor_sync(FULLM, c2, off);
    }
    if (t == 0) out[0] = part / (float)BATCH + c2 / (float)BATCH;
}

extern "C" void kernel_launch(void* const* d_in, const int* in_sizes, int n_in,
                              void* d_out, int out_size)
{
    const float* pred = (const float*)d_in[0];  // pred_coords [32,128,3]
    const float* ep   = (const float*)d_in[1];  // exist_probs [32,128]
    const float* cp   = (const float*)d_in[2];  // count_pred  [32,1]
    const float* gt   = (const float*)d_in[3];  // gt_coords   [32,64,3]
    const int*   gc   = (const int*)d_in[4];    // gt_counts   [32] int32
    const float* w    = (const float*)d_in[5];  // weight      [1,128]

    const size_t dyn = (size_t)NG * NP * sizeof(ll);   // 64 KB
    cudaFuncSetAttribute(match_loss_kernel,
                         cudaFuncAttributeMaxDynamicSharedMemorySize, (int)dyn);
    match_loss_kernel<<<BATCH, NP, dyn>>>(pred, ep, gt, w);
    reduce_kernel<<<1, 32>>>(cp, gc, (float*)d_out);
}

// round 7
// speedup vs baseline: 6.6659x; 1.1770x over previous
#include <cuda_runtime.h>
#include <math.h>

#define BATCH 32
#define NP 128
#define NG 64
#define NDIM 3
#define FULLM 0xffffffffu
#define SCALEF 1099511627776.0f   /* 2^40 — power of two: c*SCALEF is exact in f32 */
#define INF_LL (1LL << 62)

typedef long long ll;
typedef unsigned long long ull;

// per-sample (coord_loss + exist_loss) + completion counter
__device__ float g_partial[BATCH];
__device__ int   g_ctr;               // zero-init; reset by last CTA each run

// ---------------------------------------------------------------------------
// One CTA per sample. Costs are exact fixed-point int64 (f32 value * 2^40,
// truncated), low 7 bits replaced by the column index. All duals / deltas are
// multiples of 128, so c - u - v carries its column index for free. All packed
// reduced costs are nonnegative (feasible duals), so the warp argmin is a
// two-stage unsigned REDUX.MIN over (hi32, lo32). Last CTA does final reduce.
// ---------------------------------------------------------------------------
__global__ __launch_bounds__(NP, 1)
void match_loss_kernel(const float* __restrict__ pred,   // [B,NP,3]
                       const float* __restrict__ eprob,  // [B,NP]
                       const float* __restrict__ gt,     // [B,NG,3]
                       const float* __restrict__ weight, // [NP]
                       const float* __restrict__ cntp,   // [B,1]
                       const int*   __restrict__ cntg,   // [B]
                       float* __restrict__ out)
{
    extern __shared__ ll Ci[];            // [NG*NP] packed costs, 64 KB dynamic
    __shared__ float4 sp4[NP];
    __shared__ float4 sg4[NG];
    __shared__ ll     u_sh[NG + 1];
    __shared__ int    p_sh[NP + 1];       // p[j] = 1-based row matched to col j
    __shared__ int    way_sh[NP + 1];
    __shared__ ll     rpack[NG];          // packed row minima
    __shared__ int    rfree[NG + 1];
    __shared__ float  red[2 * NP];
    __shared__ int    s_last;

    const int b = blockIdx.x;
    const int t = threadIdx.x;

    // --- load coords (padded float4 for single-LDS access) ---
    {
        const float* pp = pred + (b * NP + t) * 3;
        sp4[t] = make_float4(pp[0], pp[1], pp[2], 0.f);
        if (t < NG) {
            const float* gg = gt + (b * NG + t) * 3;
            sg4[t] = make_float4(gg[0], gg[1], gg[2], 0.f);
        }
        p_sh[t] = 0;
        if (t == 0) p_sh[NP] = 0;
    }
    __syncthreads();

    // --- build packed int64 cost matrix + row minima in one pass ---
    // thread t handles row g = t>>1, columns (t&1)*64 .. +63
    {
        const int g = t >> 1;
        const int h = t & 1;
        const float4 sg = sg4[g];
        ll bp = INF_LL;
        ll* crow = &Ci[g * NP];
        #pragma unroll 8
        for (int k = 0; k < 64; k++) {
            const int q = h * 64 + k;
            const float4 sp = sp4[q];
            const float dx = sp.x - sg.x, dy = sp.y - sg.y, dz = sp.z - sg.z;
            const float c = sqrtf(dx * dx + dy * dy + dz * dz);
            const ll ci = (((ll)(c * SCALEF)) & ~127LL) | (ll)q;
            crow[q] = ci;
            if (ci < bp) bp = ci;          // ascending q: ties keep smaller q
        }
        const ll other = __shfl_xor_sync(FULLM, bp, 1);  // partner half
        if (other < bp) bp = other;        // h1 indices all > h0: tie-safe
        if (h == 0) rpack[g] = bp;
    }
    __syncthreads();

    // --- greedy tight pre-assignment: u[i] = row min (masked), v = 0 ---
    if (t == 0) {
        u_sh[0] = 0;
        for (int i = 1; i <= NG; i++) {
            const ll rp = rpack[i - 1];
            u_sh[i] = rp & ~127LL;
            const int j = (int)(rp & 127) + 1;
            if (p_sh[j] == 0) { p_sh[j] = i; rfree[i] = 0; }
            else              { rfree[i] = 1; }
        }
    }
    __syncthreads();

    // --- shortest augmenting path for leftover rows: warp 0 only ---
    if (t < 32) {
        ll v0 = 0, v1 = 0, v2 = 0, v3 = 0;          // v[4t+k+1], multiples of 128
        const ll* cbase = &Ci[4 * t];

        for (int i = 1; i <= NG; i++) {
            if (rfree[i] == 0) continue;

            // preload matched row + dual per owned column, row packed into
            // the dual's free low 7 bits (u multiple of 128, p <= 64).
            // p/u are static within one Dijkstra.
            const int pk0 = p_sh[4 * t + 1], pk1 = p_sh[4 * t + 2];
            const int pk2 = p_sh[4 * t + 3], pk3 = p_sh[4 * t + 4];
            const ll  c0 = u_sh[pk0] | (ll)pk0, c1 = u_sh[pk1] | (ll)pk1;
            const ll  c2 = u_sh[pk2] | (ll)pk2, c3 = u_sh[pk3] | (ll)pk3;

            ll m0 = INF_LL, m1 = INF_LL, m2 = INF_LL, m3 = INF_LL;
            ll d0 = 0, d1 = 0, d2 = 0, d3 = 0;      // deferred u deltas per slot
            unsigned unused = 0xFu;
            ll Dtot = 0;

            int i0 = i;
            ll  u0 = u_sh[i];
            int j0 = 0;
            int jfin = 0;

            for (int step = 0; step < 2 * (NP + 1); step++) {     // defensive cap
                const ll* cr = cbase + (i0 - 1) * NP;
                const longlong2 ca = *(const longlong2*)(cr);
                const longlong2 cb = *(const longlong2*)(cr + 2);

                // scan owned columns: cur keeps column index in low 7 bits
                if (unused & 1u) { ll cur = ca.x - u0 - v0; if (cur < m0) { m0 = cur; way_sh[4 * t + 1] = j0; } }
                if (unused & 2u) { ll cur = ca.y - u0 - v1; if (cur < m1) { m1 = cur; way_sh[4 * t + 2] = j0; } }
                if (unused & 4u) { ll cur = cb.x - u0 - v2; if (cur < m2) { m2 = cur; way_sh[4 * t + 3] = j0; } }
                if (unused & 8u) { ll cur = cb.y - u0 - v3; if (cur < m3) { m3 = cur; way_sh[4 * t + 4] = j0; } }

                // intra-lane tournament
                const ll ba = m0 < m1 ? m0 : m1;
                const ll bb = m2 < m3 ? m2 : m3;
                const ll best = ba < bb ? ba : bb;

                // two-stage unsigned warp min (all values >= 0, < 2^62)
                const unsigned hi  = (unsigned)((ull)best >> 32);
                const unsigned mh  = __reduce_min_sync(FULLM, hi);
                const unsigned lo  = (hi == mh) ? (unsigned)(ull)best : 0xFFFFFFFFu;
                const unsigned ml  = __reduce_min_sync(FULLM, lo);
                const ll bestall   = ((ll)mh << 32) | (ll)ml;

                const ll  delta = bestall & ~127LL;
                const int j1    = (int)(bestall & 127) + 1;

                // owner broadcasts packed (u[p[j1]] | p[j1]) — one 64-bit shfl
                const int owner = (j1 - 1) >> 2;
                const int slot  = (j1 - 1) & 3;
                ll comb;
                if      (slot == 0) comb = c0;
                else if (slot == 1) comb = c1;
                else if (slot == 2) comb = c2;
                else                comb = c3;
                comb = __shfl_sync(FULLM, comb, owner);
                const int i0n = (int)(comb & 127);
                const ll  u_n = comb & ~127LL;

                // updates with the OLD mask (j1 unused at update time)
                m0 -= delta; m1 -= delta; m2 -= delta; m3 -= delta;
                if (!(unused & 1u)) { v0 -= delta; d0 += delta; }
                if (!(unused & 2u)) { v1 -= delta; d1 += delta; }
                if (!(unused & 4u)) { v2 -= delta; d2 += delta; }
                if (!(unused & 8u)) { v3 -= delta; d3 += delta; }
                Dtot += delta;

                // mark j1 used on its owner lane
                if (t == owner) {
                    unused &= ~(1u << slot);
                    if      (slot == 0) m0 = INF_LL;
                    else if (slot == 1) m1 = INF_LL;
                    else if (slot == 2) m2 = INF_LL;
                    else                m3 = INF_LL;
                }

                j0 = j1; i0 = i0n; u0 = u_n;
                if (i0 == 0) { jfin = j0; break; }
            }

            // write back deferred u updates (distinct rows per used column)
            if (!(unused & 1u) && pk0 > 0) u_sh[pk0] += d0;
            if (!(unused & 2u) && pk1 > 0) u_sh[pk1] += d1;
            if (!(unused & 4u) && pk2 > 0) u_sh[pk2] += d2;
            if (!(unused & 8u) && pk3 > 0) u_sh[pk3] += d3;
            if (t == 0) u_sh[i] += Dtot;
            __syncwarp(FULLM);

            // backtrack augmenting path (lane 0); bounded defensively
            if (t == 0) {
                int jj = jfin;
                for (int s = 0; s < NP + 1 && jj != 0; s++) {
                    const int jp = way_sh[jj];
                    p_sh[jj] = (jp == 0) ? i : p_sh[jp];
                    jj = jp;
                }
            }
            __syncwarp(FULLM);
        }
    }
    __syncthreads();

    // --- losses: thread t == pred index q (identical arithmetic to R1/R4) ---
    const int q  = t;
    const int pj = p_sh[q + 1];           // 0 = unmatched, else gt row (1-based)
    float sl1 = 0.0f;
    float mask = 0.0f;
    if (pj != 0) {
        mask = 1.0f;
        const float4 sp = sp4[q];
        const float4 sg = sg4[pj - 1];
        float dd;
        dd = fabsf(sp.x - sg.x); sl1 += (dd < 1.0f) ? 0.5f * dd * dd : dd - 0.5f;
        dd = fabsf(sp.y - sg.y); sl1 += (dd < 1.0f) ? 0.5f * dd * dd : dd - 0.5f;
        dd = fabsf(sp.z - sg.z); sl1 += (dd < 1.0f) ? 0.5f * dd * dd : dd - 0.5f;
    }
    const float pr  = eprob[b * NP + q];
    const float lp  = fmaxf(logf(pr), -100.0f);
    const float l1p = fmaxf(log1pf(-pr), -100.0f);
    const float bce = -(mask * lp + (1.0f - mask) * l1p) * weight[q];

    red[t]      = sl1;
    red[NP + t] = bce;
    __syncthreads();
    #pragma unroll
    for (int s = 64; s; s >>= 1) {
        if (t < s) { red[t] += red[t + s]; red[NP + t] += red[NP + t + s]; }
        __syncthreads();
    }

    // --- publish per-sample partial; last CTA does the final reduce ---
    if (t == 0) {
        const float coord = red[0] / (float)(NG * NDIM);   // mean over (64,3)
        const float exist = red[NP] / (float)NP;           // mean over 128
        g_partial[b] = coord + exist;                      // COORD_W=EXIST_W=1
        __threadfence();
        const int old = atomicAdd(&g_ctr, 1);
        s_last = (old == BATCH - 1) ? 1 : 0;
    }
    __syncthreads();

    if (s_last && t < 32) {
        float part = g_partial[t];
        const float cd = cntp[t] - (float)cntg[t];
        float c2 = cd * cd;
        #pragma unroll
        for (int off = 16; off; off >>= 1) {
            part += __shfl_xor_sync(FULLM, part, off);
            c2   += __shfl_xor_sync(FULLM, c2, off);
        }
        if (t == 0) {
            out[0] = part / (float)BATCH + c2 / (float)BATCH;
            g_ctr = 0;                     // reset for next graph replay
        }
    }
}

extern "C" void kernel_launch(void* const* d_in, const int* in_sizes, int n_in,
                              void* d_out, int out_size)
{
    const float* pred = (const float*)d_in[0];  // pred_coords [32,128,3]
    const float* ep   = (const float*)d_in[1];  // exist_probs [32,128]
    const float* cp   = (const float*)d_in[2];  // count_pred  [32,1]
    const float* gt   = (const float*)d_in[3];  // gt_coords   [32,64,3]
    const int*   gc   = (const int*)d_in[4];    // gt_counts   [32] int32
    const float* w    = (const float*)d_in[5];  // weight      [1,128]

    const size_t dyn = (size_t)NG * NP * sizeof(ll);   // 64 KB
    cudaFuncSetAttribute(match_loss_kernel,
                         cudaFuncAttributeMaxDynamicSharedMemorySize, (int)dyn);
    match_loss_kernel<<<BATCH, NP, dyn>>>(pred, ep, gt, w, cp, gc, (float*)d_out);
}